// round 16
// baseline (speedup 1.0000x reference)
#include <cuda_runtime.h>
#include <cstddef>
#include <cstdint>

// MoEGate, 2-phase: (A) split-K GEMM with k-parity f32x2 packing
// (halves = even/odd-k partials -> both operands naturally contiguous:
// NO dup MOVs, NO weight transpose), (B) epilogue (byte-identical R15).
// x: [T=16384, h=2048] f32, W: [E=64, h] f32.
// Output (f32): [topk_idx (T*6) | topk_weight (T*6) | aux_loss (1)]
//
// R16 vs R15: expert-pair packing -> k-parity packing. Same tile
// (4 tok x 8 exp per lane, 64 FFMA2 / 12 LDS.128 per 4k) but the 16
// dup2 MOVs per 4k vanish (-17% issue slots) and the 6.2us transpose
// kernel is deleted (W consumed in natural [e][k] layout; lane le owns
// experts le+8p -> w-LDS lane stride 144B, conflict-free).
// Reduction order changes (k-parity) -> new rel_err draw; k-parity
// variants measured 8.659e-4 (pass) 3x previously.

#define NE 64
#define KTOP 6
#define NB 4
#define MAXT 16384
#define TPB 64                // tokens per GEMM block
#define THREADS 128           // 4 warps; lane = lt*8 + le
#define CHUNK 32              // k per stage
#define XPITCH 36             // floats per staged row (144B, odd/16)
#define WPITCH 36
#define EPB 64                // epilogue tokens per block
#define NBLK_C 256            // epilogue blocks = T/EPB
#define BPB 64                // epilogue blocks per batch

__device__ float    g_logits[2][MAXT * NE];      // split-K partials, 8MB
__device__ float    g_pscore[NBLK_C * NE];
__device__ int      g_pcnt[NBLK_C * NE];
__device__ unsigned g_ticket;                    // self-resetting

static __device__ __forceinline__ void ffma2(unsigned long long& d,
                                             unsigned long long a,
                                             unsigned long long b) {
    asm("fma.rn.f32x2 %0, %1, %2, %0;" : "+l"(d) : "l"(a), "l"(b));
}
static __device__ __forceinline__ void add2(unsigned long long& d,
                                            unsigned long long a) {
    asm("add.rn.f32x2 %0, %0, %1;" : "+l"(d) : "l"(a));
}
static __device__ __forceinline__ void cpa16(uint32_t dst, const void* src) {
    asm volatile("cp.async.cg.shared.global [%0], [%1], 16;"
                 :: "r"(dst), "l"(src));
}

// ---------------- A: split-K GEMM -> partial logits ----------------
__global__ __launch_bounds__(THREADS) void gemm_kernel(
    const float* __restrict__ x, const float* __restrict__ w, int h)
{
    __shared__ __align__(16) float xs[2][TPB * XPITCH];   // 18KB
    __shared__ __align__(16) float ws[2][NE * WPITCH];    // 18KB

    const int tid  = threadIdx.x;
    const int lane = tid & 31;
    const int warp = tid >> 5;
    const int lt   = lane >> 3;       // token group 0..3
    const int le   = lane & 7;        // expert lane 0..7 (owns e = le+8p)
    const int tile = blockIdx.x >> 1;
    const int kh   = blockIdx.x & 1;  // k-half
    const int tok0 = tile * TPB;
    const int kbase = kh * (h >> 1);
    const int nchunk = (h >> 1) / CHUNK;   // 32

    unsigned long long acc[4][8], sum[4][8];
#pragma unroll
    for (int j = 0; j < 4; j++)
#pragma unroll
        for (int p = 0; p < 8; p++) { acc[j][p] = 0ull; sum[j][p] = 0ull; }

    // stage: x 64 rows x 8 quads (512) + W 64 rows x 8 quads (512).
    // x smem row r = wp*16 + j*4 + lt holds token tok0 + wp*16 + lt*4 + j.
    // W staged natural: smem row e = expert e (no transpose!).
    auto stage = [&](int c, int buf) {
        const int k0 = kbase + c * CHUNK;
#pragma unroll
        for (int jj = 0; jj < 8; jj++) {
            int cj = tid + jj * THREADS;
            int r = cj >> 3, q = cj & 7;
            if (cj < 512) {
                int gtok = (r & ~15) + ((r & 3) << 2) + ((r >> 2) & 3);
                cpa16((uint32_t)__cvta_generic_to_shared(
                          &xs[buf][r * XPITCH + q * 4]),
                      x + (size_t)(tok0 + gtok) * h + k0 + q * 4);
            } else {
                int e = r - 64;
                cpa16((uint32_t)__cvta_generic_to_shared(
                          &ws[buf][e * WPITCH + q * 4]),
                      w + (size_t)e * h + k0 + q * 4);
            }
        }
    };

    stage(0, 0);
    asm volatile("cp.async.commit_group;" ::: "memory");

    for (int c = 0; c < nchunk; c++) {
        const int buf = c & 1;
        asm volatile("cp.async.wait_group 0;" ::: "memory");
        __syncthreads();
        if (c + 1 < nchunk) {
            stage(c + 1, buf ^ 1);
            asm volatile("cp.async.commit_group;" ::: "memory");
        }

        // token (lt,j) at row warp*16 + j*4 + lt; expert le+8p at row le+8p
        const float* xb = &xs[buf][(warp * 16 + lt) * XPITCH];
        const float* wb = &ws[buf][le * WPITCH];
#pragma unroll
        for (int kk = 0; kk < CHUNK; kk += 4) {
            ulonglong2 xv[4];
#pragma unroll
            for (int j = 0; j < 4; j++)
                xv[j] = *(const ulonglong2*)(xb + (j * 4) * XPITCH + kk);
            ulonglong2 wv[8];
#pragma unroll
            for (int p = 0; p < 8; p++)
                wv[p] = *(const ulonglong2*)(wb + (p * 8) * WPITCH + kk);
#pragma unroll
            for (int j = 0; j < 4; j++)
#pragma unroll
                for (int p = 0; p < 8; p++) {
                    ffma2(acc[j][p], xv[j].x, wv[p].x);
                    ffma2(acc[j][p], xv[j].y, wv[p].y);
                }
        }
        // merge 32-term chunk partials (two-level accumulation)
#pragma unroll
        for (int j = 0; j < 4; j++)
#pragma unroll
            for (int p = 0; p < 8; p++) { add2(sum[j][p], acc[j][p]); acc[j][p] = 0ull; }
    }

    // store merged (even+odd) partial logit at TRUE expert index le+8p
    float* gl = g_logits[kh];
#pragma unroll
    for (int j = 0; j < 4; j++) {
        int t = tok0 + warp * 16 + lt * 4 + j;
#pragma unroll
        for (int p = 0; p < 8; p++) {
            union { unsigned long long u; float2 f; } cv; cv.u = sum[j][p];
            gl[(size_t)t * NE + le + 8 * p] = cv.f.x + cv.f.y;
        }
    }
}

// ---------------- B: epilogue (byte-identical to R15) ----------------
__global__ __launch_bounds__(THREADS) void epi_kernel(
    float* __restrict__ out, int T, int S)
{
    __shared__ float score_acc[NE];
    __shared__ int   cnt_acc[NE];
    __shared__ unsigned is_last;
    __shared__ float part[4];

    const int tid  = threadIdx.x;
    const int lane = tid & 31;
    const int warp = tid >> 5;
    const int lt   = lane >> 3;
    const int le   = lane & 7;
    const int bid  = blockIdx.x;
    const int tok0 = bid * EPB;

    if (tid < NE) { score_acc[tid] = 0.0f; cnt_acc[tid] = 0; }
    __syncthreads();

    for (int j = 0; j < 4; j++) {
        const int t = tok0 + warp * 16 + lt * 4 + j;
        float4 a0 = *(const float4*)(g_logits[0] + (size_t)t * NE + 8 * le);
        float4 a1 = *(const float4*)(g_logits[0] + (size_t)t * NE + 8 * le + 4);
        float4 b0 = *(const float4*)(g_logits[1] + (size_t)t * NE + 8 * le);
        float4 b1 = *(const float4*)(g_logits[1] + (size_t)t * NE + 8 * le + 4);
        float v[8];
        v[0]=a0.x+b0.x; v[1]=a0.y+b0.y; v[2]=a0.z+b0.z; v[3]=a0.w+b0.w;
        v[4]=a1.x+b1.x; v[5]=a1.y+b1.y; v[6]=a1.z+b1.z; v[7]=a1.w+b1.w;

        float m = v[0];
#pragma unroll
        for (int i = 1; i < 8; i++) m = fmaxf(m, v[i]);
#pragma unroll
        for (int off = 1; off < 8; off <<= 1)
            m = fmaxf(m, __shfl_xor_sync(0xffffffffu, m, off));

        float s[8], z = 0.0f;
#pragma unroll
        for (int i = 0; i < 8; i++) { s[i] = __expf(v[i] - m); z += s[i]; }
#pragma unroll
        for (int off = 1; off < 8; off <<= 1)
            z += __shfl_xor_sync(0xffffffffu, z, off);
        float inv = 1.0f / z;
#pragma unroll
        for (int i = 0; i < 8; i++) {
            s[i] *= inv;
            atomicAdd(&score_acc[8 * le + i], s[i]);
        }

        unsigned used = 0;
        float wsum = 0.0f;
        float outw[KTOP]; int outi[KTOP];
#pragma unroll
        for (int it = 0; it < KTOP; it++) {
            float bv = -3.4e38f; int bi = 127;
#pragma unroll
            for (int i = 0; i < 8; i++) {
                bool ok = !((used >> i) & 1u) && (v[i] > bv);
                bv = ok ? v[i] : bv;
                bi = ok ? (8 * le + i) : bi;
            }
#pragma unroll
            for (int off = 1; off < 8; off <<= 1) {
                float ov = __shfl_xor_sync(0xffffffffu, bv, off);
                int   oi = __shfl_xor_sync(0xffffffffu, bi, off);
                if (ov > bv || (ov == bv && oi < bi)) { bv = ov; bi = oi; }
            }
            int ii = bi & 7;
            float cand = s[0];
#pragma unroll
            for (int i = 1; i < 8; i++) cand = (ii == i) ? s[i] : cand;
            float sc = __shfl_sync(0xffffffffu, cand, (lane & 24) | (bi >> 3));
            wsum += sc;
            outw[it] = sc; outi[it] = bi;
            if ((bi >> 3) == le) used |= 1u << (bi & 7);
            if (le == 0) atomicAdd(&cnt_acc[bi], 1);
        }
        if (le == 0) {
            float invw = 1.0f / (wsum + 1e-20f);
#pragma unroll
            for (int it = 0; it < KTOP; it++) {
                out[(size_t)t * KTOP + it] = (float)outi[it];
                out[(size_t)T * KTOP + (size_t)t * KTOP + it] = outw[it] * invw;
            }
        }
    }
    __syncthreads();

    if (tid < NE) {
        g_pscore[bid * NE + tid] = score_acc[tid];
        g_pcnt[bid * NE + tid]   = cnt_acc[tid];
    }
    __threadfence();
    __syncthreads();
    if (tid == 0) {
        unsigned tkt = atomicAdd(&g_ticket, 1u);
        is_last = (tkt == (unsigned)(gridDim.x - 1));
    }
    __syncthreads();

    if (is_last) {
        if (tid == 0) g_ticket = 0;
        __threadfence();
        float local = 0.0f;
        for (int p = tid; p < NB * NE; p += THREADS) {
            int b = p >> 6, e = p & 63;
            float sc = 0.0f; int cn = 0;
            const int base = b * BPB;
            for (int blk = 0; blk < BPB; blk++) {
                sc += g_pscore[(base + blk) * NE + e];
                cn += g_pcnt[(base + blk) * NE + e];
            }
            float ce = (float)cn * ((float)NE / ((float)S * (float)KTOP));
            local += ce * (sc / (float)S);
        }
#pragma unroll
        for (int off = 16; off; off >>= 1)
            local += __shfl_xor_sync(0xffffffffu, local, off);
        if (lane == 0) part[warp] = local;
        __syncthreads();
        if (tid == 0) {
            float sm = part[0] + part[1] + part[2] + part[3];
            out[(size_t)2 * T * KTOP] = (sm / (float)NB) * 1e-3f;
        }
    }
}

extern "C" void kernel_launch(void* const* d_in, const int* in_sizes, int n_in,
                              void* d_out, int out_size) {
    const float* x = (const float*)d_in[0];
    const float* w = (const float*)d_in[1];
    float* out = (float*)d_out;
    int h = in_sizes[1] / NE;     // 2048
    int T = in_sizes[0] / h;      // 16384
    int S = T / NB;               // 4096

    gemm_kernel<<<(T / TPB) * 2, THREADS>>>(x, w, h);
    epi_kernel<<<T / EPB, THREADS>>>(out, T, S);
}

// round 17
// speedup vs baseline: 1.1969x; 1.1969x over previous
#include <cuda_runtime.h>
#include <cstddef>
#include <cstdint>

// MoEGate, 3-phase: (A) W transpose+permute -> wT[k][perm(e)],
// (B) split-K GEMM (R15 byte-identical: expert-pair f32x2, interleaved
//     x rows), (C) epilogue with halved serial chain (256 thr) and
//     parallelized aux tail.
// x: [T=16384, h=2048] f32, W: [E=64, h] f32.
// Output (f32): [topk_idx (T*6) | topk_weight (T*6) | aux_loss (1)]
//
// R17 vs R15 (131.2us best): epilogue only. ncu showed epi = 26.9us,
// occ 10.5%, issue 16.8% -> latency-bound. 8 warps/block halve the
// per-warp shfl chain; aux tail does one (b,e) pair per thread
// (256 = NB*NE) instead of a 2-deep serial p-loop.

#define NE 64
#define KTOP 6
#define NB 4
#define MAXT 16384
#define MAXH 2048
#define TPB 64                // tokens per GEMM block
#define THREADS 128           // GEMM threads; lane = lt*8 + le
#define ETHREADS 256          // epilogue threads (8 warps)
#define CHUNK 32              // k per stage
#define XPITCH 36             // floats per staged x row
#define EPB 64                // epilogue tokens per block
#define NBLK_C 256            // epilogue blocks = T/EPB
#define BPB 64                // epilogue blocks per batch

__device__ float    g_wt[MAXH * NE];             // wT[k][perm(e)], 512KB
__device__ float    g_logits[2][MAXT * NE];      // split-K partials, 8MB
__device__ float    g_pscore[NBLK_C * NE];
__device__ int      g_pcnt[NBLK_C * NE];
__device__ unsigned g_ticket;                    // self-resetting

static __device__ __forceinline__ void ffma2(unsigned long long& d,
                                             unsigned long long a,
                                             unsigned long long b) {
    asm("fma.rn.f32x2 %0, %1, %2, %0;" : "+l"(d) : "l"(a), "l"(b));
}
static __device__ __forceinline__ void add2(unsigned long long& d,
                                            unsigned long long a) {
    asm("add.rn.f32x2 %0, %0, %1;" : "+l"(d) : "l"(a));
}
static __device__ __forceinline__ unsigned long long dup2(float f) {
    unsigned long long r;
    asm("mov.b64 %0, {%1, %1};" : "=l"(r) : "f"(f));
    return r;
}
static __device__ __forceinline__ void cpa16(uint32_t dst, const void* src) {
    asm volatile("cp.async.cg.shared.global [%0], [%1], 16;"
                 :: "r"(dst), "l"(src));
}

// ---------------- A: transpose W[e][k] -> wT[k][perm(e)] ----------------
// perm(e): e = 8*le + i  ->  (i&4)*8 + le*4 + (i&3)
__global__ void transpose_kernel(const float* __restrict__ w, int h) {
    __shared__ float s[16 * 65];
    const int k0 = blockIdx.x * 16;
    for (int idx = threadIdx.x; idx < 16 * 64; idx += 256) {
        int e = idx >> 4, kk = idx & 15;
        s[kk * 65 + e] = w[(size_t)e * h + k0 + kk];
    }
    __syncthreads();
    for (int idx = threadIdx.x; idx < 16 * 64; idx += 256) {
        int kk = idx >> 6, e = idx & 63;
        int le = e >> 3, i = e & 7;
        int pos = ((i & 4) << 3) + le * 4 + (i & 3);
        g_wt[(size_t)(k0 + kk) * NE + pos] = s[kk * 65 + e];
    }
}

// ---------------- B: split-K GEMM (R15, byte-identical) ----------------
__global__ __launch_bounds__(THREADS) void gemm_kernel(
    const float* __restrict__ x, int h)
{
    __shared__ __align__(16) float xs[2][TPB * XPITCH];   // 18KB
    __shared__ __align__(16) float wts[2][CHUNK * NE];    // 16KB

    const int tid  = threadIdx.x;
    const int lane = tid & 31;
    const int warp = tid >> 5;
    const int lt   = lane >> 3;       // token group 0..3
    const int le   = lane & 7;        // expert group 0..7
    const int tile = blockIdx.x >> 1;
    const int kh   = blockIdx.x & 1;  // k-half
    const int tok0 = tile * TPB;
    const int kbase = kh * (h >> 1);
    const int nchunk = (h >> 1) / CHUNK;   // 32

    unsigned long long acc[4][4], sum[4][4];
#pragma unroll
    for (int j = 0; j < 4; j++)
#pragma unroll
        for (int p = 0; p < 4; p++) { acc[j][p] = 0ull; sum[j][p] = 0ull; }

    auto stage = [&](int c, int buf) {
        const int k0 = kbase + c * CHUNK;
#pragma unroll
        for (int j = 0; j < 8; j++) {
            int cj = tid + j * THREADS;
            if (cj < 512) {
                int r = cj >> 3, q = cj & 7;
                int gtok = (r & ~15) + ((r & 3) << 2) + ((r >> 2) & 3);
                cpa16((uint32_t)__cvta_generic_to_shared(
                          &xs[buf][r * XPITCH + q * 4]),
                      x + (size_t)(tok0 + gtok) * h + k0 + q * 4);
            } else {
                int c2 = cj - 512;
                int k = c2 >> 4, q = c2 & 15;
                cpa16((uint32_t)__cvta_generic_to_shared(
                          &wts[buf][k * NE + q * 4]),
                      g_wt + (size_t)(k0 + k) * NE + q * 4);
            }
        }
    };

    stage(0, 0);
    asm volatile("cp.async.commit_group;" ::: "memory");

    for (int c = 0; c < nchunk; c++) {
        const int buf = c & 1;
        asm volatile("cp.async.wait_group 0;" ::: "memory");
        __syncthreads();
        if (c + 1 < nchunk) {
            stage(c + 1, buf ^ 1);
            asm volatile("cp.async.commit_group;" ::: "memory");
        }

        const float* xb = &xs[buf][(warp * 16 + lt) * XPITCH];
        const float* wb = &wts[buf][le * 4];   // wlo at +0, whi at +32
#pragma unroll
        for (int kk = 0; kk < CHUNK; kk += 4) {
            float4 xv0 = *(const float4*)(xb + 0 * XPITCH + kk);
            float4 xv1 = *(const float4*)(xb + 4 * XPITCH + kk);
            float4 xv2 = *(const float4*)(xb + 8 * XPITCH + kk);
            float4 xv3 = *(const float4*)(xb + 12 * XPITCH + kk);
#pragma unroll
            for (int k2 = 0; k2 < 4; k2++) {
                ulonglong2 wlo = *(const ulonglong2*)(wb + (kk + k2) * NE);
                ulonglong2 whi = *(const ulonglong2*)(wb + (kk + k2) * NE + 32);
                unsigned long long d0 = dup2(((const float*)&xv0)[k2]);
                unsigned long long d1 = dup2(((const float*)&xv1)[k2]);
                unsigned long long d2 = dup2(((const float*)&xv2)[k2]);
                unsigned long long d3 = dup2(((const float*)&xv3)[k2]);
                ffma2(acc[0][0], d0, wlo.x); ffma2(acc[0][1], d0, wlo.y);
                ffma2(acc[0][2], d0, whi.x); ffma2(acc[0][3], d0, whi.y);
                ffma2(acc[1][0], d1, wlo.x); ffma2(acc[1][1], d1, wlo.y);
                ffma2(acc[1][2], d1, whi.x); ffma2(acc[1][3], d1, whi.y);
                ffma2(acc[2][0], d2, wlo.x); ffma2(acc[2][1], d2, wlo.y);
                ffma2(acc[2][2], d2, whi.x); ffma2(acc[2][3], d2, whi.y);
                ffma2(acc[3][0], d3, wlo.x); ffma2(acc[3][1], d3, wlo.y);
                ffma2(acc[3][2], d3, whi.x); ffma2(acc[3][3], d3, whi.y);
            }
        }
#pragma unroll
        for (int j = 0; j < 4; j++)
#pragma unroll
            for (int p = 0; p < 4; p++) { add2(sum[j][p], acc[j][p]); acc[j][p] = 0ull; }
    }

    float* gl = g_logits[kh];
#pragma unroll
    for (int j = 0; j < 4; j++) {
        int t = tok0 + warp * 16 + lt * 4 + j;
#pragma unroll
        for (int p = 0; p < 4; p++) {
            union { unsigned long long u; float2 f; } cv; cv.u = sum[j][p];
            *(float2*)(gl + (size_t)t * NE + 8 * le + 2 * p) = cv.f;
        }
    }
}

// ---------------- C: epilogue (256 threads, j-loop 2, parallel aux) ----------------
__global__ __launch_bounds__(ETHREADS) void epi_kernel(
    float* __restrict__ out, int T, int S)
{
    __shared__ float score_acc[NE];
    __shared__ int   cnt_acc[NE];
    __shared__ unsigned is_last;
    __shared__ float part[8];

    const int tid  = threadIdx.x;
    const int lane = tid & 31;
    const int warp = tid >> 5;        // 0..7
    const int lt   = lane >> 3;
    const int le   = lane & 7;
    const int bid  = blockIdx.x;
    const int tok0 = bid * EPB;

    if (tid < NE) { score_acc[tid] = 0.0f; cnt_acc[tid] = 0; }
    __syncthreads();

    for (int j = 0; j < 2; j++) {
        const int t = tok0 + warp * 8 + lt * 2 + j;   // bijection onto 64 tokens
        float4 a0 = *(const float4*)(g_logits[0] + (size_t)t * NE + 8 * le);
        float4 a1 = *(const float4*)(g_logits[0] + (size_t)t * NE + 8 * le + 4);
        float4 b0 = *(const float4*)(g_logits[1] + (size_t)t * NE + 8 * le);
        float4 b1 = *(const float4*)(g_logits[1] + (size_t)t * NE + 8 * le + 4);
        float v[8];
        v[0]=a0.x+b0.x; v[1]=a0.y+b0.y; v[2]=a0.z+b0.z; v[3]=a0.w+b0.w;
        v[4]=a1.x+b1.x; v[5]=a1.y+b1.y; v[6]=a1.z+b1.z; v[7]=a1.w+b1.w;

        float m = v[0];
#pragma unroll
        for (int i = 1; i < 8; i++) m = fmaxf(m, v[i]);
#pragma unroll
        for (int off = 1; off < 8; off <<= 1)
            m = fmaxf(m, __shfl_xor_sync(0xffffffffu, m, off));

        float s[8], z = 0.0f;
#pragma unroll
        for (int i = 0; i < 8; i++) { s[i] = __expf(v[i] - m); z += s[i]; }
#pragma unroll
        for (int off = 1; off < 8; off <<= 1)
            z += __shfl_xor_sync(0xffffffffu, z, off);
        float inv = 1.0f / z;
#pragma unroll
        for (int i = 0; i < 8; i++) {
            s[i] *= inv;
            atomicAdd(&score_acc[8 * le + i], s[i]);
        }

        unsigned used = 0;
        float wsum = 0.0f;
        float outw[KTOP]; int outi[KTOP];
#pragma unroll
        for (int it = 0; it < KTOP; it++) {
            float bv = -3.4e38f; int bi = 127;
#pragma unroll
            for (int i = 0; i < 8; i++) {
                bool ok = !((used >> i) & 1u) && (v[i] > bv);
                bv = ok ? v[i] : bv;
                bi = ok ? (8 * le + i) : bi;
            }
#pragma unroll
            for (int off = 1; off < 8; off <<= 1) {
                float ov = __shfl_xor_sync(0xffffffffu, bv, off);
                int   oi = __shfl_xor_sync(0xffffffffu, bi, off);
                if (ov > bv || (ov == bv && oi < bi)) { bv = ov; bi = oi; }
            }
            int ii = bi & 7;
            float cand = s[0];
#pragma unroll
            for (int i = 1; i < 8; i++) cand = (ii == i) ? s[i] : cand;
            float sc = __shfl_sync(0xffffffffu, cand, (lane & 24) | (bi >> 3));
            wsum += sc;
            outw[it] = sc; outi[it] = bi;
            if ((bi >> 3) == le) used |= 1u << (bi & 7);
            if (le == 0) atomicAdd(&cnt_acc[bi], 1);
        }
        if (le == 0) {
            float invw = 1.0f / (wsum + 1e-20f);
#pragma unroll
            for (int it = 0; it < KTOP; it++) {
                out[(size_t)t * KTOP + it] = (float)outi[it];
                out[(size_t)T * KTOP + (size_t)t * KTOP + it] = outw[it] * invw;
            }
        }
    }
    __syncthreads();

    if (tid < NE) {
        g_pscore[bid * NE + tid] = score_acc[tid];
        g_pcnt[bid * NE + tid]   = cnt_acc[tid];
    }
    __threadfence();
    __syncthreads();
    if (tid == 0) {
        unsigned tkt = atomicAdd(&g_ticket, 1u);
        is_last = (tkt == (unsigned)(gridDim.x - 1));
    }
    __syncthreads();

    if (is_last) {
        if (tid == 0) g_ticket = 0;
        __threadfence();
        // one (b,e) pair per thread: 256 threads = NB*NE
        const int b = tid >> 6, e = tid & 63;
        float sc = 0.0f; int cn = 0;
        const int base = b * BPB;
#pragma unroll 8
        for (int blk = 0; blk < BPB; blk++) {
            sc += g_pscore[(base + blk) * NE + e];
            cn += g_pcnt[(base + blk) * NE + e];
        }
        float ce = (float)cn * ((float)NE / ((float)S * (float)KTOP));
        float local = ce * (sc / (float)S);
#pragma unroll
        for (int off = 16; off; off >>= 1)
            local += __shfl_xor_sync(0xffffffffu, local, off);
        if (lane == 0) part[warp] = local;
        __syncthreads();
        if (tid == 0) {
            float sm = 0.0f;
#pragma unroll
            for (int i = 0; i < 8; i++) sm += part[i];
            out[(size_t)2 * T * KTOP] = (sm / (float)NB) * 1e-3f;
        }
    }
}

extern "C" void kernel_launch(void* const* d_in, const int* in_sizes, int n_in,
                              void* d_out, int out_size) {
    const float* x = (const float*)d_in[0];
    const float* w = (const float*)d_in[1];
    float* out = (float*)d_out;
    int h = in_sizes[1] / NE;     // 2048
    int T = in_sizes[0] / h;      // 16384
    int S = T / NB;               // 4096

    transpose_kernel<<<h / 16, 256>>>(w, h);
    gemm_kernel<<<(T / TPB) * 2, THREADS>>>(x, h);
    epi_kernel<<<T / EPB, ETHREADS>>>(out, T, S);
}